// round 6
// baseline (speedup 1.0000x reference)
#include <cuda_runtime.h>
#include <cuda_fp16.h>
#include <math.h>
#include <math_constants.h>

#define IMG   512
#define NB    16
#define OT    74          // owned (output) tile
#define RG    96          // region = OT + 2*HALO
#define HALO  11          // 1 (boundary) + 10 (dilation cascade)
#define TPD   7
#define NTILES (NB*TPD*TPD)   // 784
#define RSTR  97          // half2 row stride (odd -> conflict-free col walks)
#define CSTR  75          // center buffer half2 stride (odd)
#define NTHR  576         // 18 warps; 2 CTAs/SM
#define PXT   16          // 96*96/576
#define SEG   16          // cascade rows/cols per thread (96/6)

#define OFF_B   (RG*RSTR)            // 9312 (half2 units)
#define OFF_C   (2*RG*RSTR)          // 18624
#define OFF_RED (OFF_C + OT*CSTR)    // 24174
#define SMEM_H2 (OFF_RED + 104)      // 104 half2 units = 104 floats >= 97 used
#define SMEM_BYTES (SMEM_H2*4)       // ~94.8 KB -> 2 CTAs/SM

// per-tile partials: [tile][0]=bce [1]=hd [2]=p [3]=t [4]=pt (fully rewritten every launch)
__device__ float g_part[NTILES*5];
__device__ unsigned g_count;   // last-CTA counter; finisher resets to 0

__global__ void __launch_bounds__(NTHR, 2)
k_main(const float* __restrict__ logits, const int* __restrict__ target,
       float* __restrict__ out) {
    extern __shared__ __half2 sm[];
    __half2* A  = sm;            // temp (v-pass out) / raw (p,t)
    __half2* B  = sm + OFF_B;    // current (pred,gt) maps
    __half2* C  = sm + OFF_C;    // center boundaries (pred_b, gt_b), 74x74
    float*   red = (float*)(sm + OFF_RED);

    const int tid  = threadIdx.x;
    const int tile = blockIdx.x;
    const int b    = tile / (TPD * TPD);
    const int tr   = tile % (TPD * TPD);
    const int tyi  = tr / TPD, txi = tr % TPD;
    const int oy   = tyi * OT - HALO, ox = txi * OT - HALO;
    const bool interior = (oy >= 0) & (ox >= 0) & (oy + RG <= IMG) & (ox + RG <= IMG);

    const float* lg = logits + (size_t)b * IMG * IMG;
    const int*   tg = target + (size_t)b * IMG * IMG;

    const __half   hNI = __ushort_as_half((unsigned short)0xFC00);  // -inf
    const __half   hPI = __ushort_as_half((unsigned short)0x7C00);  // +inf
    const __half2  hNEG = __halves2half2(hNI, hNI);
    const __half2  hPOS = __halves2half2(hPI, hPI);

    float a_bce = 0.f, a_p = 0.f, a_t = 0.f, a_pt = 0.f, a_hd = 0.f;

    // ---- load: A = half2(sigmoid(x), t); elementwise loss partials on owned px
#pragma unroll
    for (int k = 0; k < PXT; k++) {
        int idx = tid + k * NTHR;
        int r = idx / RG, c = idx - r * RG;
        int iy = oy + r, ix = ox + c;
        bool in = interior || ((iy >= 0) & (iy < IMG) & (ix >= 0) & (ix < IMG));
        float p = 0.f, t = 0.f;
        if (in) {
            float x = lg[iy * IMG + ix];
            t = (float)tg[iy * IMG + ix];
            p = 1.f / (1.f + expf(-x));
            if ((r >= HALO) & (r < HALO + OT) & (c >= HALO) & (c < HALO + OT)) {
                a_bce += fmaxf(x, 0.f) - x * t + log1pf(expf(-fabsf(x)));
                a_p += p; a_t += t; a_pt += p * t;
            }
        }
        A[r * RSTR + c] = __floats2half2_rn(p, t);
    }
    __syncthreads();

    // ---- boundary: B = maxpool3 - minpool3 (-inf outside image)
#pragma unroll
    for (int k = 0; k < PXT; k++) {
        int idx = tid + k * NTHR;
        int r = idx / RG, c = idx - r * RG;
        int iy = oy + r, ix = ox + c;
        bool cin = interior || ((iy >= 0) & (iy < IMG) & (ix >= 0) & (ix < IMG));
        __half2 bnd = hNEG;
        if (cin) {
            __half2 mx = hNEG, mn = hPOS;
#pragma unroll
            for (int dr = -1; dr <= 1; dr++) {
                int rr = r + dr; rr = rr < 0 ? 0 : (rr > RG - 1 ? RG - 1 : rr);
                bool rin = interior || ((oy + rr >= 0) & (oy + rr < IMG));
#pragma unroll
                for (int dc = -1; dc <= 1; dc++) {
                    int cc = c + dc; cc = cc < 0 ? 0 : (cc > RG - 1 ? RG - 1 : cc);
                    bool nin = rin && (interior || ((ox + cc >= 0) & (ox + cc < IMG)));
                    __half2 v = A[rr * RSTR + cc];
                    mx = __hmax2(mx, nin ? v : hNEG);
                    mn = __hmin2(mn, nin ? v : hPOS);
                }
            }
            bnd = __hsub2(mx, mn);
        }
        B[r * RSTR + c] = bnd;
        if ((r >= HALO) & (r < HALO + OT) & (c >= HALO) & (c < HALO + OT))
            C[(r - HALO) * CSTR + (c - HALO)] = bnd;
    }
    __syncthreads();

    // ---- dilation cascade: maxpool_{2d+1} via iterated separable 3x3, d = 1..10
    {
        const int cA  = tid % RG;  const int rA0 = (tid / RG) * SEG;
        const int rB  = tid % RG;  const int cB0 = (tid / RG) * SEG;
        const bool rowown = (rB >= HALO) & (rB < HALO + OT) & ((oy + rB) < IMG);
        const int chi = (HALO + OT) < (IMG - ox) ? (HALO + OT) : (IMG - ox);
        const __half2* crow = C + (rB - HALO) * CSTR;

        for (int d = 1; d <= 10; d++) {
            // vertical max3: A = vmax3(B), SEG rows of column cA
            {
                __half2 prev = B[(rA0 > 0 ? rA0 - 1 : 0) * RSTR + cA];
                __half2 cur  = B[rA0 * RSTR + cA];
#pragma unroll
                for (int i = 0; i < SEG; i++) {
                    int r = rA0 + i;
                    __half2 nxt = B[(r < RG - 1 ? r + 1 : RG - 1) * RSTR + cA];
                    A[r * RSTR + cA] = __hmax2(prev, __hmax2(cur, nxt));
                    prev = cur; cur = nxt;
                }
            }
            __syncthreads();
            // horizontal max3: B = hmax3(A), fused |.| accumulation on owned px
            {
                __half2 prev = A[rB * RSTR + (cB0 > 0 ? cB0 - 1 : 0)];
                __half2 cur  = A[rB * RSTR + cB0];
                float s = 0.f;
#pragma unroll
                for (int i = 0; i < SEG; i++) {
                    int c = cB0 + i;
                    __half2 nxt = A[rB * RSTR + (c < RG - 1 ? c + 1 : RG - 1)];
                    __half2 v = __hmax2(prev, __hmax2(cur, nxt));
                    B[rB * RSTR + c] = v;
                    if (rowown & (c >= HALO) & (c < chi)) {
                        // cc = (pred_b, gt_b); need |pred_d-gt_b| + |gt_d-pred_b|
                        __half2 cc = __lowhigh2highlow(crow[c - HALO]);
                        float2 f = __half22float2(__habs2(__hsub2(v, cc)));
                        s += f.x + f.y;
                    }
                    prev = cur; cur = nxt;
                }
                a_hd += (0.1f * (float)d) * s;
            }
            __syncthreads();
        }
    }

    // ---- block reduction -> per-tile partials
    const unsigned FULL = 0xffffffffu;
#pragma unroll
    for (int o = 16; o; o >>= 1) {
        a_bce += __shfl_down_sync(FULL, a_bce, o);
        a_hd  += __shfl_down_sync(FULL, a_hd,  o);
        a_p   += __shfl_down_sync(FULL, a_p,   o);
        a_t   += __shfl_down_sync(FULL, a_t,   o);
        a_pt  += __shfl_down_sync(FULL, a_pt,  o);
    }
    int lane = tid & 31, w = tid >> 5;               // 18 warps
    if (lane == 0) {
        red[w] = a_bce; red[18 + w] = a_hd; red[36 + w] = a_p;
        red[54 + w] = a_t; red[72 + w] = a_pt;
    }
    __syncthreads();
    if (tid == 0) {
        float sb = 0, sh = 0, sp = 0, st = 0, spt = 0;
#pragma unroll
        for (int i = 0; i < 18; i++) {
            sb += red[i]; sh += red[18 + i]; sp += red[36 + i];
            st += red[54 + i]; spt += red[72 + i];
        }
        float* g = &g_part[tile * 5];
        g[0] = sb; g[1] = sh; g[2] = sp; g[3] = st; g[4] = spt;
        __threadfence();
        unsigned v = atomicAdd(&g_count, 1u);
        red[96] = (v == NTILES - 1) ? 1.f : 0.f;
    }
    __syncthreads();

    // ---- last CTA performs the final combine (single-launch pipeline)
    if (red[96] != 0.f) {
        __threadfence();
        __shared__ float simg[16][2];   // (1-dice), ft per image
        __shared__ float sbh[16][2];    // bce, hd per image
        for (int img = w; img < 16; img += 18) {
            float bce = 0, hd = 0, p = 0, t = 0, pt = 0;
            for (int i = lane; i < TPD * TPD; i += 32) {
                const float* g = &g_part[(img * TPD * TPD + i) * 5];
                bce += g[0]; hd += g[1]; p += g[2]; t += g[3]; pt += g[4];
            }
#pragma unroll
            for (int o = 16; o; o >>= 1) {
                bce += __shfl_down_sync(FULL, bce, o);
                hd  += __shfl_down_sync(FULL, hd,  o);
                p   += __shfl_down_sync(FULL, p,   o);
                t   += __shfl_down_sync(FULL, t,   o);
                pt  += __shfl_down_sync(FULL, pt,  o);
            }
            if (lane == 0) {
                float dice = (2.f * pt + 1e-6f) / (p + t + 1e-6f + 1e-7f);
                float FP = p - pt, FN = t - pt;
                float tv = (pt + 1e-6f) / (pt + 0.7f * FP + 0.3f * FN + 1e-6f + 1e-7f);
                simg[img][0] = 1.f - dice;
                simg[img][1] = powf(fmaxf(1.f - tv, 0.f), 0.75f);
                sbh[img][0] = bce; sbh[img][1] = hd;
            }
        }
        __syncthreads();
        if (tid == 0) {
            float ds = 0, fs = 0, sb = 0, sh = 0;
#pragma unroll
            for (int i = 0; i < 16; i++) {
                ds += simg[i][0]; fs += simg[i][1];
                sb += sbh[i][0];  sh += sbh[i][1];
            }
            const float N = (float)NB * IMG * IMG;
            out[0] = sb / N + ds / 16.f + fs / 16.f +
                     0.1f * ((sh / N) / (5.5f + 1e-8f));
            g_count = 0;   // self-reset for next graph replay
        }
    }
}

extern "C" void kernel_launch(void* const* d_in, const int* in_sizes, int n_in,
                              void* d_out, int out_size) {
    const float* logits = (const float*)d_in[0];
    const int*   target = (const int*)d_in[1];
    cudaFuncSetAttribute(k_main, cudaFuncAttributeMaxDynamicSharedMemorySize, SMEM_BYTES);
    k_main<<<NTILES, NTHR, SMEM_BYTES>>>(logits, target, (float*)d_out);
}

// round 7
// speedup vs baseline: 1.2899x; 1.2899x over previous
#include <cuda_runtime.h>
#include <cuda_fp16.h>
#include <math.h>

#define IMG   512
#define NB    16
#define OT    74
#define RGR   96
#define HALO  11
#define TPD   7
#define NTILES (NB*TPD*TPD)
#define ROWW  48          // half2 words per row (96 px)
#define RSTRW 52          // row stride in words (16B aligned, conflict-free)
#define MAPW  (RGR*RSTRW)
#define NTHR  576

#define P0 0
#define G0 MAPW
#define P1 (2*MAPW)
#define G1 (3*MAPW)
#define CBASE (4*MAPW)
#define CSZ  (OT*RSTRW)
#define REDW (CBASE + 2*CSZ)
#define TOTW (REDW + 104)
#define SMEM_BYTES (TOTW*4)   // 111072 B -> 2 CTAs/SM

#define NEGU  0xFC00FC00u
#define FULLM 0xFFFFFFFFu
#define SHW(a,b) __byte_perm((a),(b),0x5432)

// keep-masks for owned px per [edge][chunk][sub][word]; owned px = 11..84 (78 at right edge)
__constant__ unsigned ACCM[2][3][2][8] = {
 { { {0,0,0,0,0,0xFFFF0000u,FULLM,FULLM}, {FULLM,FULLM,FULLM,FULLM,FULLM,FULLM,FULLM,FULLM} },
   { {FULLM,FULLM,FULLM,FULLM,FULLM,FULLM,FULLM,FULLM}, {FULLM,FULLM,FULLM,FULLM,FULLM,FULLM,FULLM,FULLM} },
   { {FULLM,FULLM,FULLM,FULLM,FULLM,FULLM,FULLM,FULLM}, {FULLM,FULLM,0x0000FFFFu,0,0,0,0,0} } },
 { { {0,0,0,0,0,0xFFFF0000u,FULLM,FULLM}, {FULLM,FULLM,FULLM,FULLM,FULLM,FULLM,FULLM,FULLM} },
   { {FULLM,FULLM,FULLM,FULLM,FULLM,FULLM,FULLM,FULLM}, {FULLM,FULLM,FULLM,FULLM,FULLM,FULLM,FULLM,FULLM} },
   { {FULLM,FULLM,FULLM,FULLM,FULLM,FULLM,FULLM,0x0000FFFFu}, {0,0,0,0,0,0,0,0} } }
};

__device__ float g_part[NTILES*5];
__device__ unsigned g_count;

__device__ __forceinline__ unsigned hmax2u(unsigned a, unsigned b) {
    __half2 r = __hmax2(*(__half2*)&a, *(__half2*)&b); return *(unsigned*)&r; }
__device__ __forceinline__ unsigned hmin2u(unsigned a, unsigned b) {
    __half2 r = __hmin2(*(__half2*)&a, *(__half2*)&b); return *(unsigned*)&r; }
__device__ __forceinline__ unsigned max3w(unsigned a, unsigned b, unsigned c) {
    return hmax2u(a, hmax2u(b, c)); }
__device__ __forceinline__ unsigned habsdiff2u(unsigned a, unsigned b) {
    __half2 r = __habs2(__hsub2(*(__half2*)&a, *(__half2*)&b)); return *(unsigned*)&r; }
__device__ __forceinline__ unsigned hadd2u(unsigned a, unsigned b) {
    __half2 r = __hadd2(*(__half2*)&a, *(__half2*)&b); return *(unsigned*)&r; }

__global__ void __launch_bounds__(NTHR, 2)
k_main(const float* __restrict__ logits, const int* __restrict__ target,
       float* __restrict__ out) {
    extern __shared__ unsigned smu[];
    float* red = (float*)(smu + REDW);

    const int tid  = threadIdx.x;
    const int tile = blockIdx.x;
    const int b    = tile / (TPD*TPD);
    const int tr   = tile % (TPD*TPD);
    const int tyi  = tr / TPD, txi = tr % TPD;
    const int oy   = tyi*OT - HALO, ox = txi*OT - HALO;

    const float* lg = logits + (size_t)b*IMG*IMG;
    const int*   tg = target + (size_t)b*IMG*IMG;

    float a_bce = 0.f, a_p = 0.f, a_t = 0.f, a_pt = 0.f, a_hd = 0.f;

    // ---- load: replicate-clamped; P0 = pred (2 px/word), G0 = gt; owned-px partials
#pragma unroll
    for (int k = 0; k < 8; k++) {
        int idx = tid + k*NTHR;
        int r = idx / ROWW, w = idx - r*ROWW;
        int iy = oy + r, iyc = min(max(iy,0), IMG-1);
        int px0 = 2*w, ix0 = ox + px0, ix1 = ix0 + 1;
        int ixc0 = min(max(ix0,0), IMG-1), ixc1 = min(max(ix1,0), IMG-1);
        float x0 = lg[iyc*IMG+ixc0], x1 = lg[iyc*IMG+ixc1];
        float t0 = (float)tg[iyc*IMG+ixc0], t1 = (float)tg[iyc*IMG+ixc1];
        float p0 = 1.f/(1.f+expf(-x0)), p1 = 1.f/(1.f+expf(-x1));
        bool rown = (r >= HALO) & (r < HALO+OT) & (iy < IMG);
        if (rown & (px0 >= HALO) & (px0 < HALO+OT) & (ix0 < IMG)) {
            a_bce += fmaxf(x0,0.f) - x0*t0 + log1pf(expf(-fabsf(x0)));
            a_p += p0; a_t += t0; a_pt += p0*t0;
        }
        if (rown & (px0+1 >= HALO) & (px0+1 < HALO+OT) & (ix1 < IMG)) {
            a_bce += fmaxf(x1,0.f) - x1*t1 + log1pf(expf(-fabsf(x1)));
            a_p += p1; a_t += t1; a_pt += p1*t1;
        }
        __half2 hp = __floats2half2_rn(p0,p1), ht = __floats2half2_rn(t0,t1);
        smu[P0 + r*RSTRW + w] = *(unsigned*)&hp;
        smu[G0 + r*RSTRW + w] = *(unsigned*)&ht;
    }
    __syncthreads();

    // ---- thread mappings
    const int m  = tid / 288;           // 0=pred map, 1=gt map
    const int s  = tid % 288;
    const int rr = s % RGR, ch = s / RGR;        // hpass/boundary: row + 16-word chunk
    const int cg = s % 12,  rb = s / 12;          // vpass: uint4 col group + 4-row group
    const int vcol = cg*4, vr0 = rb*4;
    const int vm1 = rb ? vr0-1 : 0;
    const int vp4 = (rb == 23) ? RGR-1 : vr0+4;
    unsigned* rawS = smu + (m ? G0 : P0);
    unsigned* bndD = smu + (m ? G1 : P1);
    unsigned* myC  = smu + CBASE + m*CSZ;
    unsigned* otC  = smu + CBASE + (1-m)*CSZ;
    const bool rowown = (rr >= HALO) & (rr < HALO+OT) & ((oy+rr) < IMG);
    const int msel = (txi == TPD-1) ? 1 : 0;

    // ---- boundary: maxpool3 - minpool3 (vectorized), -inf at out-of-image px
    {
        int rm1 = rr ? rr-1 : 0, rp1 = (rr < RGR-1) ? rr+1 : RGR-1;
        bool rowin = ((unsigned)(oy+rr)) < (unsigned)IMG;
        bool colEdge = (txi == 0) | (txi == TPD-1);
        int rs[3] = {rm1, rr, rp1};
#pragma unroll
        for (int sc = 0; sc < 2; sc++) {
            int wb = ch*16 + sc*8;
            unsigned vx[10], vn[10];
#pragma unroll
            for (int q = 0; q < 3; q++) {
                int bq = rs[q]*RSTRW + wb;
                uint4 A = *(const uint4*)(rawS+bq), Bv = *(const uint4*)(rawS+bq+4);
                unsigned em = wb ? rawS[bq-1] : A.x;
                unsigned ep = (wb+8 < ROWW) ? rawS[bq+8] : Bv.w;
                unsigned row[10] = {em,A.x,A.y,A.z,A.w,Bv.x,Bv.y,Bv.z,Bv.w,ep};
#pragma unroll
                for (int i = 0; i < 10; i++) {
                    if (q == 0) { vx[i] = row[i]; vn[i] = row[i]; }
                    else { vx[i] = hmax2u(vx[i],row[i]); vn[i] = hmin2u(vn[i],row[i]); }
                }
            }
            unsigned o[8];
#pragma unroll
            for (int i = 0; i < 8; i++) {
                unsigned hx = max3w(vx[i+1], SHW(vx[i],vx[i+1]), SHW(vx[i+1],vx[i+2]));
                unsigned hn = hmin2u(vn[i+1], hmin2u(SHW(vn[i],vn[i+1]), SHW(vn[i+1],vn[i+2])));
                __half2 bh = __hsub2(*(__half2*)&hx, *(__half2*)&hn);
                unsigned bnd = *(unsigned*)&bh;
                if (colEdge) {
                    int p0 = ox + 2*(wb+i);
                    unsigned keep = (((unsigned)p0 < IMG) ? 0x0000FFFFu : 0u)
                                  | (((unsigned)(p0+1) < IMG) ? 0xFFFF0000u : 0u);
                    bnd = (bnd & keep) | (NEGU & ~keep);
                }
                o[i] = rowin ? bnd : NEGU;
            }
            int base = rr*RSTRW + wb;
            *(uint4*)(bndD+base)   = make_uint4(o[0],o[1],o[2],o[3]);
            *(uint4*)(bndD+base+4) = make_uint4(o[4],o[5],o[6],o[7]);
            if ((rr >= HALO) & (rr < HALO+OT)) {
                int cb = (rr-HALO)*RSTRW + wb;
                *(uint4*)(myC+cb)   = make_uint4(o[0],o[1],o[2],o[3]);
                *(uint4*)(myC+cb+4) = make_uint4(o[4],o[5],o[6],o[7]);
            }
        }
    }
    __syncthreads();

    // ---- dilation cascade d = 1..10 (ping-pong bndD <-> rawS)
    {
        unsigned* srcB = bndD;
        unsigned* tmpB = rawS;
        for (int d = 1; d <= 10; d++) {
            { // vertical max3: srcB -> tmpB
                uint4 a = *(const uint4*)(srcB + vm1*RSTRW + vcol);
                uint4 bb = *(const uint4*)(srcB + vr0*RSTRW + vcol);
#pragma unroll
                for (int j = 0; j < 4; j++) {
                    int rn = (j < 3) ? vr0+j+1 : vp4;
                    uint4 c = *(const uint4*)(srcB + rn*RSTRW + vcol);
                    uint4 o;
                    o.x = max3w(a.x,bb.x,c.x); o.y = max3w(a.y,bb.y,c.y);
                    o.z = max3w(a.z,bb.z,c.z); o.w = max3w(a.w,bb.w,c.w);
                    *(uint4*)(tmpB + (vr0+j)*RSTRW + vcol) = o;
                    a = bb; bb = c;
                }
            }
            __syncthreads();
            { // horizontal max3: tmpB -> srcB, fused masked |diff| accumulation
                float sd = 0.f;
#pragma unroll
                for (int sc = 0; sc < 2; sc++) {
                    int wb = ch*16 + sc*8, base = rr*RSTRW + wb;
                    uint4 A = *(const uint4*)(tmpB+base), Bv = *(const uint4*)(tmpB+base+4);
                    unsigned em = wb ? tmpB[base-1] : A.x;
                    unsigned ep = (wb+8 < ROWW) ? tmpB[base+8] : Bv.w;
                    unsigned w[10] = {em,A.x,A.y,A.z,A.w,Bv.x,Bv.y,Bv.z,Bv.w,ep};
                    unsigned o[8];
#pragma unroll
                    for (int i = 0; i < 8; i++)
                        o[i] = max3w(w[i+1], SHW(w[i],w[i+1]), SHW(w[i+1],w[i+2]));
                    *(uint4*)(srcB+base)   = make_uint4(o[0],o[1],o[2],o[3]);
                    *(uint4*)(srcB+base+4) = make_uint4(o[4],o[5],o[6],o[7]);
                    if (rowown) {
                        int cb = (rr-HALO)*RSTRW + wb;
                        uint4 C1 = *(const uint4*)(otC+cb), C2 = *(const uint4*)(otC+cb+4);
                        unsigned cw[8] = {C1.x,C1.y,C1.z,C1.w,C2.x,C2.y,C2.z,C2.w};
                        unsigned acc = 0u;
#pragma unroll
                        for (int i = 0; i < 8; i++)
                            acc = hadd2u(acc, habsdiff2u(o[i],cw[i]) & ACCM[msel][ch][sc][i]);
                        float2 f = __half22float2(*(__half2*)&acc);
                        sd += f.x + f.y;
                    }
                }
                a_hd += (0.1f*(float)d) * sd;
            }
            __syncthreads();
        }
    }

    // ---- block reduction -> per-tile partials
    const unsigned FULL = 0xffffffffu;
#pragma unroll
    for (int o = 16; o; o >>= 1) {
        a_bce += __shfl_down_sync(FULL,a_bce,o); a_hd += __shfl_down_sync(FULL,a_hd,o);
        a_p += __shfl_down_sync(FULL,a_p,o); a_t += __shfl_down_sync(FULL,a_t,o);
        a_pt += __shfl_down_sync(FULL,a_pt,o);
    }
    int lane = tid & 31, w = tid >> 5;
    if (lane == 0) {
        red[w] = a_bce; red[18+w] = a_hd; red[36+w] = a_p;
        red[54+w] = a_t; red[72+w] = a_pt;
    }
    __syncthreads();
    if (tid == 0) {
        float sb=0, sh=0, sp=0, st=0, spt=0;
#pragma unroll
        for (int i = 0; i < 18; i++) {
            sb += red[i]; sh += red[18+i]; sp += red[36+i];
            st += red[54+i]; spt += red[72+i];
        }
        float* g = &g_part[tile*5];
        g[0]=sb; g[1]=sh; g[2]=sp; g[3]=st; g[4]=spt;
        __threadfence();
        unsigned v = atomicAdd(&g_count, 1u);
        red[96] = (v == NTILES-1) ? 1.f : 0.f;
    }
    __syncthreads();

    // ---- last CTA: final combine
    if (red[96] != 0.f) {
        __threadfence();
        __shared__ float simg[16][2], sbh[16][2];
        for (int img = w; img < 16; img += 18) {
            float bce=0, hd=0, p=0, t=0, pt=0;
            for (int i = lane; i < TPD*TPD; i += 32) {
                const float* g = &g_part[(img*TPD*TPD+i)*5];
                bce += g[0]; hd += g[1]; p += g[2]; t += g[3]; pt += g[4];
            }
#pragma unroll
            for (int o = 16; o; o >>= 1) {
                bce += __shfl_down_sync(FULL,bce,o); hd += __shfl_down_sync(FULL,hd,o);
                p += __shfl_down_sync(FULL,p,o); t += __shfl_down_sync(FULL,t,o);
                pt += __shfl_down_sync(FULL,pt,o);
            }
            if (lane == 0) {
                float dice = (2.f*pt + 1e-6f) / (p + t + 1e-6f + 1e-7f);
                float FP = p - pt, FN = t - pt;
                float tv = (pt + 1e-6f) / (pt + 0.7f*FP + 0.3f*FN + 1e-6f + 1e-7f);
                simg[img][0] = 1.f - dice;
                simg[img][1] = powf(fmaxf(1.f - tv, 0.f), 0.75f);
                sbh[img][0] = bce; sbh[img][1] = hd;
            }
        }
        __syncthreads();
        if (tid == 0) {
            float ds=0, fs=0, sb=0, sh=0;
#pragma unroll
            for (int i = 0; i < 16; i++) {
                ds += simg[i][0]; fs += simg[i][1];
                sb += sbh[i][0];  sh += sbh[i][1];
            }
            const float N = (float)NB*IMG*IMG;
            out[0] = sb/N + ds/16.f + fs/16.f + 0.1f*((sh/N)/(5.5f + 1e-8f));
            g_count = 0;
        }
    }
}

extern "C" void kernel_launch(void* const* d_in, const int* in_sizes, int n_in,
                              void* d_out, int out_size) {
    const float* logits = (const float*)d_in[0];
    const int*   target = (const int*)d_in[1];
    cudaFuncSetAttribute(k_main, cudaFuncAttributeMaxDynamicSharedMemorySize, SMEM_BYTES);
    k_main<<<NTILES, NTHR, SMEM_BYTES>>>(logits, target, (float*)d_out);
}